// round 3
// baseline (speedup 1.0000x reference)
#include <cuda_runtime.h>
#include <math.h>

#define NV_MAX 100000
#define CAP    128          // max in-degree bucket capacity
#define NPB    16           // nodes per block (one warp each, 512 threads)

#define EPS_F    1e-8f
#define WEIGHT_D 0.01

// Packed node data: one 32B-aligned struct per node -> single L2 sector per gather.
// a = (mu0.x, mu0.y, mu0.z, mu.x), b = (mu.y, mu.z, 0, 0)
struct __align__(32) Pack {
    float4 a;
    float4 b;
};

__device__ Pack   g_pack[NV_MAX];
__device__ int    g_cur[NV_MAX];          // per-node edge cursor / final degree
__device__ int    g_slot[NV_MAX * CAP];   // bucketed neighbor ids (j) per source node i
__device__ double g_acc[3];               // [0]=W, [1]=A, [2]=cross
__device__ unsigned int g_done;

// ---------------------------------------------------------------------------
// K0: pack positions, zero cursors + accumulators
// ---------------------------------------------------------------------------
__global__ void init_kernel(const float* __restrict__ mu0, const float* __restrict__ mu, int n) {
    int t = blockIdx.x * blockDim.x + threadIdx.x;
    if (t < n) {
        Pack p;
        p.a = make_float4(mu0[3 * t], mu0[3 * t + 1], mu0[3 * t + 2], mu[3 * t]);
        p.b = make_float4(mu[3 * t + 1], mu[3 * t + 2], 0.0f, 0.0f);
        g_pack[t] = p;
        g_cur[t] = 0;
    }
    if (t < 3) g_acc[t] = 0.0;
    if (t == 3) g_done = 0u;
}

// ---------------------------------------------------------------------------
// K1: bucket fill — one int atomic + one 4B store per edge
// ---------------------------------------------------------------------------
__global__ void fill_kernel(const int* __restrict__ eidx, int e) {
    int t = blockIdx.x * blockDim.x + threadIdx.x;   // group of 4 edges
    int base = t * 4;
    if (base >= e) return;
    int4 ii = *reinterpret_cast<const int4*>(eidx + base);
    int4 jj = *reinterpret_cast<const int4*>(eidx + e + base);
    #pragma unroll
    for (int k = 0; k < 4; ++k) {
        int i = (&ii.x)[k];
        int j = (&jj.x)[k];
        int p = atomicAdd(&g_cur[i], 1);
        if (p < CAP) g_slot[i * CAP + p] = j;
    }
}

// ---------------------------------------------------------------------------
// K2: warp-per-node gather + per-thread polar + loss reduction (+ epilogue)
// ---------------------------------------------------------------------------
__global__ void __launch_bounds__(NPB * 32) node_kernel(int n, float* __restrict__ out) {
    const int w    = threadIdx.x >> 5;          // warp in block = node slot
    const int lane = threadIdx.x & 31;
    const int node = blockIdx.x * NPB + w;

    __shared__ float sS[NPB][12];               // 9 S entries + W + A per node

    float m00 = 0.f, m01 = 0.f, m02 = 0.f;
    float m10 = 0.f, m11 = 0.f, m12 = 0.f;
    float m20 = 0.f, m21 = 0.f, m22 = 0.f;
    float Wl = 0.f, Al = 0.f;

    if (node < n) {
        int deg = g_cur[node];
        if (deg > CAP) deg = CAP;
        Pack pi = g_pack[node];
        const int* slot = &g_slot[node * CAP];

        for (int k = lane; k < deg; k += 32) {
            int j = slot[k];                     // coalesced 128B line per warp
            Pack pj = g_pack[j];                 // 32-wide random gather (full MLP)
            float rx = pj.a.x - pi.a.x;
            float ry = pj.a.y - pi.a.y;
            float rz = pj.a.z - pi.a.z;
            float dx = pj.a.w - pi.a.w;
            float dy = pj.b.x - pi.b.x;
            float dz = pj.b.y - pi.b.y;
            float rr = rx * rx + ry * ry + rz * rz;
            float ww = 1.0f / (sqrtf(rr) + EPS_F);
            Wl += ww;
            Al += ww * (rr + dx * dx + dy * dy + dz * dz);
            float wdx = ww * dx, wdy = ww * dy, wdz = ww * dz;
            m00 += wdx * rx;  m01 += wdx * ry;  m02 += wdx * rz;
            m10 += wdy * rx;  m11 += wdy * ry;  m12 += wdy * rz;
            m20 += wdz * rx;  m21 += wdz * ry;  m22 += wdz * rz;
        }
    }

    // warp butterfly reduction of 11 partials
    #pragma unroll
    for (int o = 16; o > 0; o >>= 1) {
        m00 += __shfl_xor_sync(0xFFFFFFFFu, m00, o);
        m01 += __shfl_xor_sync(0xFFFFFFFFu, m01, o);
        m02 += __shfl_xor_sync(0xFFFFFFFFu, m02, o);
        m10 += __shfl_xor_sync(0xFFFFFFFFu, m10, o);
        m11 += __shfl_xor_sync(0xFFFFFFFFu, m11, o);
        m12 += __shfl_xor_sync(0xFFFFFFFFu, m12, o);
        m20 += __shfl_xor_sync(0xFFFFFFFFu, m20, o);
        m21 += __shfl_xor_sync(0xFFFFFFFFu, m21, o);
        m22 += __shfl_xor_sync(0xFFFFFFFFu, m22, o);
        Wl  += __shfl_xor_sync(0xFFFFFFFFu, Wl,  o);
        Al  += __shfl_xor_sync(0xFFFFFFFFu, Al,  o);
    }
    if (lane == 0) {
        sS[w][0] = m00; sS[w][1] = m01; sS[w][2] = m02;
        sS[w][3] = m10; sS[w][4] = m11; sS[w][5] = m12;
        sS[w][6] = m20; sS[w][7] = m21; sS[w][8] = m22;
        sS[w][9] = Wl;  sS[w][10] = Al;
    }
    __syncthreads();

    // threads 0..NPB-1 (all in warp 0): one polar decomposition each
    float cl = 0.f, Wt = 0.f, At = 0.f;
    if (threadIdx.x < NPB) {
        int nd = blockIdx.x * NPB + threadIdx.x;
        if (nd < n) {
            float s00 = sS[threadIdx.x][0], s01 = sS[threadIdx.x][1], s02 = sS[threadIdx.x][2];
            float s10 = sS[threadIdx.x][3], s11 = sS[threadIdx.x][4], s12 = sS[threadIdx.x][5];
            float s20 = sS[threadIdx.x][6], s21 = sS[threadIdx.x][7], s22 = sS[threadIdx.x][8];
            Wt = sS[threadIdx.x][9];
            At = sS[threadIdx.x][10];

            float fr = s00*s00 + s01*s01 + s02*s02 +
                       s10*s10 + s11*s11 + s12*s12 +
                       s20*s20 + s21*s21 + s22*s22;
            if (fr > 1e-30f) {
                float inv = rsqrtf(fr);
                float x00 = s00*inv, x01 = s01*inv, x02 = s02*inv;
                float x10 = s10*inv, x11 = s11*inv, x12 = s12*inv;
                float x20 = s20*inv, x21 = s21*inv, x22 = s22*inv;

                float detm = s00 * (s11*s22 - s12*s21)
                           - s01 * (s10*s22 - s12*s20)
                           + s02 * (s10*s21 - s11*s20);

                // scaled Newton polar iteration: X <- 0.5*(z*X + (1/(z*det))*C)
                #pragma unroll 1
                for (int it = 0; it < 14; ++it) {
                    float c00 = x11*x22 - x12*x21;
                    float c01 = x12*x20 - x10*x22;
                    float c02 = x10*x21 - x11*x20;
                    float c10 = x02*x21 - x01*x22;
                    float c11 = x00*x22 - x02*x20;
                    float c12 = x01*x20 - x00*x21;
                    float c20 = x01*x12 - x02*x11;
                    float c21 = x02*x10 - x00*x12;
                    float c22 = x00*x11 - x01*x10;
                    float det = x00*c00 + x01*c01 + x02*c02;
                    float ad  = fabsf(det);
                    if (ad < 1e-12f) break;
                    float z  = rcbrtf(ad);
                    float hz = 0.5f * z;
                    float hi = 0.5f / (z * det);
                    x00 = hz*x00 + hi*c00;  x01 = hz*x01 + hi*c01;  x02 = hz*x02 + hi*c02;
                    x10 = hz*x10 + hi*c10;  x11 = hz*x11 + hi*c11;  x12 = hz*x12 + hi*c12;
                    x20 = hz*x20 + hi*c20;  x21 = hz*x21 + hi*c21;  x22 = hz*x22 + hi*c22;
                    if (fabsf(ad - 1.0f) < 1e-6f) break;
                }

                if (detm < 0.0f) {  // R <- R * diag(-1,1,1): negate column 0
                    x00 = -x00; x10 = -x10; x20 = -x20;
                }
                cl = x00*s00 + x01*s01 + x02*s02 +
                     x10*s10 + x11*s11 + x12*s12 +
                     x20*s20 + x21*s21 + x22*s22;
            }
        }
    }

    // reduce NPB contributions within warp 0 (other lanes hold zeros)
    if (w == 0) {
        #pragma unroll
        for (int o = 16; o > 0; o >>= 1) {
            cl += __shfl_down_sync(0xFFFFFFFFu, cl, o);
            Wt += __shfl_down_sync(0xFFFFFFFFu, Wt, o);
            At += __shfl_down_sync(0xFFFFFFFFu, At, o);
        }
        if (lane == 0) {
            atomicAdd(&g_acc[0], (double)Wt);
            atomicAdd(&g_acc[1], (double)At);
            atomicAdd(&g_acc[2], (double)cl);
        }
    }

    // last-block epilogue: compute the scalar loss in-kernel
    __shared__ unsigned int s_ticket;
    __threadfence();
    if (threadIdx.x == 0) s_ticket = atomicAdd(&g_done, 1u);
    __syncthreads();
    if (threadIdx.x == 0 && s_ticket == gridDim.x - 1) {
        double W = g_acc[0];
        double A = g_acc[1];
        double C = g_acc[2];
        out[0] = (float)(WEIGHT_D * (A - 2.0 * C) / W);
    }
}

// ---------------------------------------------------------------------------
extern "C" void kernel_launch(void* const* d_in, const int* in_sizes, int n_in,
                              void* d_out, int out_size) {
    const float* mu0 = (const float*)d_in[0];
    const float* mu  = (const float*)d_in[1];
    const int* eidx  = (const int*)d_in[2];
    int n = in_sizes[0] / 3;
    int e = in_sizes[2] / 2;

    init_kernel<<<(n + 255) / 256, 256>>>(mu0, mu, n);
    fill_kernel<<<(e / 4 + 255) / 256, 256>>>(eidx, e);
    node_kernel<<<(n + NPB - 1) / NPB, NPB * 32>>>(n, (float*)d_out);
}

// round 5
// speedup vs baseline: 1.3250x; 1.3250x over previous
#include <cuda_runtime.h>
#include <math.h>

#define NV_MAX 100000
#define CAP    128          // max in-degree bucket capacity
#define EPS_F    1e-8f
#define WEIGHT_D 0.01

// Packed node data: one 32B-aligned struct per node -> single L2 line per gather.
// a = (mu0.x, mu0.y, mu0.z, mu.x), b = (mu.y, mu.z, 0, 0)
struct __align__(32) Pack {
    float4 a;
    float4 b;
};

__device__ Pack   g_pack[NV_MAX];
__device__ int    g_cur[NV_MAX];          // per-node cursor; zero at rest (restored each replay)
__device__ int    g_slot[NV_MAX * CAP];   // bucketed neighbor ids per source node
__device__ double g_acc[3];               // [0]=W, [1]=A, [2]=cross; zero at rest
__device__ unsigned int g_done;           // zero at rest

// ---------------------------------------------------------------------------
// K1: fused pack + bucket-fill. Blocks [0, bpack) pack nodes; the rest fill
// edge buckets (independent: fill touches only g_cur/g_slot, pack only g_pack).
// ---------------------------------------------------------------------------
__global__ void fused_fill_kernel(const float* __restrict__ mu0,
                                  const float* __restrict__ mu,
                                  const int* __restrict__ eidx,
                                  int n, int e, int bpack) {
    if ((int)blockIdx.x < bpack) {
        int t = blockIdx.x * blockDim.x + threadIdx.x;
        if (t < n) {
            Pack p;
            p.a = make_float4(mu0[3 * t], mu0[3 * t + 1], mu0[3 * t + 2], mu[3 * t]);
            p.b = make_float4(mu[3 * t + 1], mu[3 * t + 2], 0.0f, 0.0f);
            g_pack[t] = p;
        }
        return;
    }
    int t = (blockIdx.x - bpack) * blockDim.x + threadIdx.x;   // group of 4 edges
    int base = t * 4;
    if (base + 4 <= e) {
        int4 ii = *reinterpret_cast<const int4*>(eidx + base);
        int4 jj = *reinterpret_cast<const int4*>(eidx + e + base);
        #pragma unroll
        for (int k = 0; k < 4; ++k) {
            int i = (&ii.x)[k];
            int j = (&jj.x)[k];
            int p = atomicAdd(&g_cur[i], 1);
            if (p < CAP) g_slot[i * CAP + p] = j;
        }
    } else {
        for (int q = base; q < e; ++q) {
            int i = eidx[q];
            int j = eidx[e + q];
            int p = atomicAdd(&g_cur[i], 1);
            if (p < CAP) g_slot[i * CAP + p] = j;
        }
    }
}

// ---------------------------------------------------------------------------
// helper: accumulate one neighbor pack into the 3x3 covariance + W/A
// ---------------------------------------------------------------------------
#define ACC_ONE(pa, pb)                                                        \
    {                                                                          \
        float rx = (pa).x - pia.x, ry = (pa).y - pia.y, rz = (pa).z - pia.z;   \
        float dx = (pa).w - pia.w, dy = (pb).x - pib.x, dz = (pb).y - pib.y;   \
        float rr = rx * rx + ry * ry + rz * rz;                                \
        float ww = 1.0f / (sqrtf(rr) + EPS_F);                                 \
        Wl += ww;                                                              \
        Al += ww * (rr + dx * dx + dy * dy + dz * dz);                         \
        float wdx = ww * dx, wdy = ww * dy, wdz = ww * dz;                     \
        m00 += wdx * rx; m01 += wdx * ry; m02 += wdx * rz;                     \
        m10 += wdy * rx; m11 += wdy * ry; m12 += wdy * rz;                     \
        m20 += wdz * rx; m21 += wdz * ry; m22 += wdz * rz;                     \
    }

// ---------------------------------------------------------------------------
// K2: thread-per-node gather (batch-8, high MLP) + polar + reduction + epilogue
// ---------------------------------------------------------------------------
__global__ void __launch_bounds__(128) node_kernel(int n, float* __restrict__ out) {
    int t = blockIdx.x * blockDim.x + threadIdx.x;
    float Wl = 0.f, Al = 0.f, cl = 0.f;
    if (t < n) {
        int deg = g_cur[t];
        g_cur[t] = 0;                         // restore rest state for next replay
        if (deg > CAP) deg = CAP;
        Pack pi = g_pack[t];
        float4 pia = pi.a, pib = pi.b;
        const int* slot = &g_slot[t * CAP];

        float m00 = 0.f, m01 = 0.f, m02 = 0.f;
        float m10 = 0.f, m11 = 0.f, m12 = 0.f;
        float m20 = 0.f, m21 = 0.f, m22 = 0.f;

        int k = 0;
        for (; k + 8 <= deg; k += 8) {
            // 2 coalesced-per-thread index loads, then 16 independent gathers
            int4 j0 = *reinterpret_cast<const int4*>(slot + k);
            int4 j1 = *reinterpret_cast<const int4*>(slot + k + 4);
            float4 a0 = g_pack[j0.x].a, b0 = g_pack[j0.x].b;
            float4 a1 = g_pack[j0.y].a, b1 = g_pack[j0.y].b;
            float4 a2 = g_pack[j0.z].a, b2 = g_pack[j0.z].b;
            float4 a3 = g_pack[j0.w].a, b3 = g_pack[j0.w].b;
            float4 a4 = g_pack[j1.x].a, b4 = g_pack[j1.x].b;
            float4 a5 = g_pack[j1.y].a, b5 = g_pack[j1.y].b;
            float4 a6 = g_pack[j1.z].a, b6 = g_pack[j1.z].b;
            float4 a7 = g_pack[j1.w].a, b7 = g_pack[j1.w].b;
            ACC_ONE(a0, b0) ACC_ONE(a1, b1) ACC_ONE(a2, b2) ACC_ONE(a3, b3)
            ACC_ONE(a4, b4) ACC_ONE(a5, b5) ACC_ONE(a6, b6) ACC_ONE(a7, b7)
        }
        for (; k < deg; ++k) {
            int j = slot[k];
            float4 pa = g_pack[j].a, pb = g_pack[j].b;
            ACC_ONE(pa, pb)
        }

        float fr = m00*m00 + m01*m01 + m02*m02 +
                   m10*m10 + m11*m11 + m12*m12 +
                   m20*m20 + m21*m21 + m22*m22;
        if (fr > 1e-30f) {
            float inv = rsqrtf(fr);
            float x00 = m00*inv, x01 = m01*inv, x02 = m02*inv;
            float x10 = m10*inv, x11 = m11*inv, x12 = m12*inv;
            float x20 = m20*inv, x21 = m21*inv, x22 = m22*inv;

            float detm = m00 * (m11*m22 - m12*m21)
                       - m01 * (m10*m22 - m12*m20)
                       + m02 * (m10*m21 - m11*m20);

            // scaled Newton polar iteration: X <- 0.5*(z*X + (1/(z*det))*C)
            #pragma unroll 1
            for (int it = 0; it < 14; ++it) {
                float c00 = x11*x22 - x12*x21;
                float c01 = x12*x20 - x10*x22;
                float c02 = x10*x21 - x11*x20;
                float c10 = x02*x21 - x01*x22;
                float c11 = x00*x22 - x02*x20;
                float c12 = x01*x20 - x00*x21;
                float c20 = x01*x12 - x02*x11;
                float c21 = x02*x10 - x00*x12;
                float c22 = x00*x11 - x01*x10;
                float det = x00*c00 + x01*c01 + x02*c02;
                float ad  = fabsf(det);
                if (ad < 1e-12f) break;
                float z  = rcbrtf(ad);
                float hz = 0.5f * z;
                float hi = 0.5f / (z * det);
                x00 = hz*x00 + hi*c00;  x01 = hz*x01 + hi*c01;  x02 = hz*x02 + hi*c02;
                x10 = hz*x10 + hi*c10;  x11 = hz*x11 + hi*c11;  x12 = hz*x12 + hi*c12;
                x20 = hz*x20 + hi*c20;  x21 = hz*x21 + hi*c21;  x22 = hz*x22 + hi*c22;
                if (fabsf(ad - 1.0f) < 1e-6f) break;
            }

            if (detm < 0.0f) {  // R <- R * diag(-1,1,1): negate column 0
                x00 = -x00; x10 = -x10; x20 = -x20;
            }
            cl = x00*m00 + x01*m01 + x02*m02 +
                 x10*m10 + x11*m11 + x12*m12 +
                 x20*m20 + x21*m21 + x22*m22;
        }
    }

    // block reduction of (Wl, Al, cl)
    #pragma unroll
    for (int o = 16; o > 0; o >>= 1) {
        Wl += __shfl_down_sync(0xFFFFFFFFu, Wl, o);
        Al += __shfl_down_sync(0xFFFFFFFFu, Al, o);
        cl += __shfl_down_sync(0xFFFFFFFFu, cl, o);
    }
    __shared__ float sa[4], sb[4], sc[4];
    int lane = threadIdx.x & 31;
    int wid  = threadIdx.x >> 5;
    if (lane == 0) { sa[wid] = Wl; sb[wid] = Al; sc[wid] = cl; }
    __syncthreads();
    if (wid == 0) {
        Wl = (lane < 4) ? sa[lane] : 0.0f;
        Al = (lane < 4) ? sb[lane] : 0.0f;
        cl = (lane < 4) ? sc[lane] : 0.0f;
        #pragma unroll
        for (int o = 2; o > 0; o >>= 1) {
            Wl += __shfl_down_sync(0xFFFFFFFFu, Wl, o);
            Al += __shfl_down_sync(0xFFFFFFFFu, Al, o);
            cl += __shfl_down_sync(0xFFFFFFFFu, cl, o);
        }
        if (lane == 0) {
            atomicAdd(&g_acc[0], (double)Wl);
            atomicAdd(&g_acc[1], (double)Al);
            atomicAdd(&g_acc[2], (double)cl);
        }
    }

    // last-block epilogue: scalar loss + restore accumulators to rest state
    __shared__ unsigned int s_ticket;
    __threadfence();
    if (threadIdx.x == 0) s_ticket = atomicAdd(&g_done, 1u);
    __syncthreads();
    if (threadIdx.x == 0 && s_ticket == gridDim.x - 1) {
        double W = g_acc[0];
        double A = g_acc[1];
        double C = g_acc[2];
        out[0] = (float)(WEIGHT_D * (A - 2.0 * C) / W);
        g_acc[0] = 0.0; g_acc[1] = 0.0; g_acc[2] = 0.0;
        g_done = 0u;
    }
}

// ---------------------------------------------------------------------------
extern "C" void kernel_launch(void* const* d_in, const int* in_sizes, int n_in,
                              void* d_out, int out_size) {
    const float* mu0 = (const float*)d_in[0];
    const float* mu  = (const float*)d_in[1];
    const int* eidx  = (const int*)d_in[2];
    int n = in_sizes[0] / 3;
    int e = in_sizes[2] / 2;

    int bpack = (n + 255) / 256;
    int bfill = ((e + 3) / 4 + 255) / 256;
    fused_fill_kernel<<<bpack + bfill, 256>>>(mu0, mu, eidx, n, e, bpack);
    node_kernel<<<(n + 127) / 128, 128>>>(n, (float*)d_out);
}

// round 6
// speedup vs baseline: 1.3888x; 1.0481x over previous
#include <cuda_runtime.h>
#include <math.h>

#define NV_MAX 100000
#define CAP    128          // max in-degree bucket capacity
#define EPS_F    1e-8f
#define WEIGHT_D 0.01

// Packed node data: one 32B-aligned struct per node -> single L2 line per gather.
// a = (mu0.x, mu0.y, mu0.z, mu.x), b = (mu.y, mu.z, 0, 0)
struct __align__(32) Pack {
    float4 a;
    float4 b;
};

__device__ Pack   g_pack[NV_MAX];
__device__ int    g_cur[NV_MAX];          // per-node cursor; zero at rest (restored each replay)
__device__ int    g_slot[NV_MAX * CAP];   // bucketed neighbor ids per source node
__device__ double g_acc[3];               // [0]=W, [1]=A, [2]=cross; zero at rest
__device__ unsigned int g_done;           // zero at rest

// ---------------------------------------------------------------------------
// K1: fused pack + bucket-fill. Blocks [0, bpack) pack nodes; the rest fill
// edge buckets (independent: fill touches only g_cur/g_slot, pack only g_pack).
// ---------------------------------------------------------------------------
__global__ void fused_fill_kernel(const float* __restrict__ mu0,
                                  const float* __restrict__ mu,
                                  const int* __restrict__ eidx,
                                  int n, int e, int bpack) {
    if ((int)blockIdx.x < bpack) {
        int t = blockIdx.x * blockDim.x + threadIdx.x;
        if (t < n) {
            Pack p;
            p.a = make_float4(mu0[3 * t], mu0[3 * t + 1], mu0[3 * t + 2], mu[3 * t]);
            p.b = make_float4(mu[3 * t + 1], mu[3 * t + 2], 0.0f, 0.0f);
            g_pack[t] = p;
        }
        return;
    }
    int t = (blockIdx.x - bpack) * blockDim.x + threadIdx.x;   // group of 4 edges
    int base = t * 4;
    if (base + 4 <= e) {
        int4 ii = *reinterpret_cast<const int4*>(eidx + base);
        int4 jj = *reinterpret_cast<const int4*>(eidx + e + base);
        #pragma unroll
        for (int k = 0; k < 4; ++k) {
            int i = (&ii.x)[k];
            int j = (&jj.x)[k];
            int p = atomicAdd(&g_cur[i], 1);
            if (p < CAP) g_slot[i * CAP + p] = j;
        }
    } else {
        for (int q = base; q < e; ++q) {
            int i = eidx[q];
            int j = eidx[e + q];
            int p = atomicAdd(&g_cur[i], 1);
            if (p < CAP) g_slot[i * CAP + p] = j;
        }
    }
}

// ---------------------------------------------------------------------------
// helper: accumulate one neighbor pack into the 3x3 covariance + W/A
// ---------------------------------------------------------------------------
#define ACC_ONE(pa, pb)                                                        \
    {                                                                          \
        float rx = (pa).x - pia.x, ry = (pa).y - pia.y, rz = (pa).z - pia.z;   \
        float dx = (pa).w - pia.w, dy = (pb).x - pib.x, dz = (pb).y - pib.y;   \
        float rr = rx * rx + ry * ry + rz * rz;                                \
        float ww = 1.0f / (sqrtf(rr) + EPS_F);                                 \
        Wl += ww;                                                              \
        Al += ww * (rr + dx * dx + dy * dy + dz * dz);                         \
        float wdx = ww * dx, wdy = ww * dy, wdz = ww * dz;                     \
        m00 += wdx * rx; m01 += wdx * ry; m02 += wdx * rz;                     \
        m10 += wdy * rx; m11 += wdy * ry; m12 += wdy * rz;                     \
        m20 += wdz * rx; m21 += wdz * ry; m22 += wdz * rz;                     \
    }

// ---------------------------------------------------------------------------
// K2: quad-per-node gather (4 threads/node) + polar on sub 0 + reduction
// ---------------------------------------------------------------------------
__global__ void __launch_bounds__(256) node_kernel(int n, float* __restrict__ out) {
    int tid  = blockIdx.x * blockDim.x + threadIdx.x;
    int node = tid >> 2;          // 4 threads per node
    int sub  = tid & 3;

    float Wl = 0.f, Al = 0.f, cl = 0.f;
    float m00 = 0.f, m01 = 0.f, m02 = 0.f;
    float m10 = 0.f, m11 = 0.f, m12 = 0.f;
    float m20 = 0.f, m21 = 0.f, m22 = 0.f;
    int deg = 0;

    if (node < n) {
        deg = g_cur[node];
        if (sub == 0) g_cur[node] = 0;       // restore rest state for next replay
        if (deg > CAP) deg = CAP;
        Pack pi = g_pack[node];
        float4 pia = pi.a, pib = pi.b;
        const int* slot = &g_slot[node * CAP];

        // main: sub handles int4-aligned chunks base = sub*4 + 16*m
        for (int base = sub * 4; base + 4 <= deg; base += 16) {
            int4 jj = *reinterpret_cast<const int4*>(slot + base);
            float4 a0 = g_pack[jj.x].a, b0 = g_pack[jj.x].b;
            float4 a1 = g_pack[jj.y].a, b1 = g_pack[jj.y].b;
            float4 a2 = g_pack[jj.z].a, b2 = g_pack[jj.z].b;
            float4 a3 = g_pack[jj.w].a, b3 = g_pack[jj.w].b;
            ACC_ONE(a0, b0) ACC_ONE(a1, b1) ACC_ONE(a2, b2) ACC_ONE(a3, b3)
        }
        // tail: [deg&~3, deg), size < 4, one element per sub
        int k = (deg & ~3) + sub;
        if (k < deg) {
            int j = slot[k];
            float4 pa = g_pack[j].a, pb = g_pack[j].b;
            ACC_ONE(pa, pb)
        }
    }

    // reduce the 11 partials within the quad (xor 1, 2 stays inside the quad)
    #pragma unroll
    for (int o = 1; o <= 2; o <<= 1) {
        m00 += __shfl_xor_sync(0xFFFFFFFFu, m00, o);
        m01 += __shfl_xor_sync(0xFFFFFFFFu, m01, o);
        m02 += __shfl_xor_sync(0xFFFFFFFFu, m02, o);
        m10 += __shfl_xor_sync(0xFFFFFFFFu, m10, o);
        m11 += __shfl_xor_sync(0xFFFFFFFFu, m11, o);
        m12 += __shfl_xor_sync(0xFFFFFFFFu, m12, o);
        m20 += __shfl_xor_sync(0xFFFFFFFFu, m20, o);
        m21 += __shfl_xor_sync(0xFFFFFFFFu, m21, o);
        m22 += __shfl_xor_sync(0xFFFFFFFFu, m22, o);
        Wl  += __shfl_xor_sync(0xFFFFFFFFu, Wl,  o);
        Al  += __shfl_xor_sync(0xFFFFFFFFu, Al,  o);
    }

    // sub 0 runs the polar decomposition for its node
    if (node < n && sub == 0) {
        float fr = m00*m00 + m01*m01 + m02*m02 +
                   m10*m10 + m11*m11 + m12*m12 +
                   m20*m20 + m21*m21 + m22*m22;
        if (fr > 1e-30f) {
            float inv = rsqrtf(fr);
            float x00 = m00*inv, x01 = m01*inv, x02 = m02*inv;
            float x10 = m10*inv, x11 = m11*inv, x12 = m12*inv;
            float x20 = m20*inv, x21 = m21*inv, x22 = m22*inv;

            float detm = m00 * (m11*m22 - m12*m21)
                       - m01 * (m10*m22 - m12*m20)
                       + m02 * (m10*m21 - m11*m20);

            // scaled Newton polar iteration: X <- 0.5*(z*X + (1/(z*det))*C)
            #pragma unroll 1
            for (int it = 0; it < 14; ++it) {
                float c00 = x11*x22 - x12*x21;
                float c01 = x12*x20 - x10*x22;
                float c02 = x10*x21 - x11*x20;
                float c10 = x02*x21 - x01*x22;
                float c11 = x00*x22 - x02*x20;
                float c12 = x01*x20 - x00*x21;
                float c20 = x01*x12 - x02*x11;
                float c21 = x02*x10 - x00*x12;
                float c22 = x00*x11 - x01*x10;
                float det = x00*c00 + x01*c01 + x02*c02;
                float ad  = fabsf(det);
                if (ad < 1e-12f) break;
                float z  = rcbrtf(ad);
                float hz = 0.5f * z;
                float hi = 0.5f / (z * det);
                x00 = hz*x00 + hi*c00;  x01 = hz*x01 + hi*c01;  x02 = hz*x02 + hi*c02;
                x10 = hz*x10 + hi*c10;  x11 = hz*x11 + hi*c11;  x12 = hz*x12 + hi*c12;
                x20 = hz*x20 + hi*c20;  x21 = hz*x21 + hi*c21;  x22 = hz*x22 + hi*c22;
                if (fabsf(ad - 1.0f) < 1e-6f) break;
            }

            if (detm < 0.0f) {  // R <- R * diag(-1,1,1): negate column 0
                x00 = -x00; x10 = -x10; x20 = -x20;
            }
            cl = x00*m00 + x01*m01 + x02*m02 +
                 x10*m10 + x11*m11 + x12*m12 +
                 x20*m20 + x21*m21 + x22*m22;
        }
    } else {
        Wl = 0.f; Al = 0.f; cl = 0.f;     // only sub 0 contributes
    }

    // block reduction of (Wl, Al, cl)
    #pragma unroll
    for (int o = 16; o > 0; o >>= 1) {
        Wl += __shfl_down_sync(0xFFFFFFFFu, Wl, o);
        Al += __shfl_down_sync(0xFFFFFFFFu, Al, o);
        cl += __shfl_down_sync(0xFFFFFFFFu, cl, o);
    }
    __shared__ float sa[8], sb[8], sc[8];
    int lane = threadIdx.x & 31;
    int wid  = threadIdx.x >> 5;
    if (lane == 0) { sa[wid] = Wl; sb[wid] = Al; sc[wid] = cl; }
    __syncthreads();
    if (wid == 0) {
        Wl = (lane < 8) ? sa[lane] : 0.0f;
        Al = (lane < 8) ? sb[lane] : 0.0f;
        cl = (lane < 8) ? sc[lane] : 0.0f;
        #pragma unroll
        for (int o = 4; o > 0; o >>= 1) {
            Wl += __shfl_down_sync(0xFFFFFFFFu, Wl, o);
            Al += __shfl_down_sync(0xFFFFFFFFu, Al, o);
            cl += __shfl_down_sync(0xFFFFFFFFu, cl, o);
        }
        if (lane == 0) {
            atomicAdd(&g_acc[0], (double)Wl);
            atomicAdd(&g_acc[1], (double)Al);
            atomicAdd(&g_acc[2], (double)cl);
        }
    }

    // last-block epilogue: scalar loss + restore accumulators to rest state
    __shared__ unsigned int s_ticket;
    __threadfence();
    if (threadIdx.x == 0) s_ticket = atomicAdd(&g_done, 1u);
    __syncthreads();
    if (threadIdx.x == 0 && s_ticket == gridDim.x - 1) {
        double W = g_acc[0];
        double A = g_acc[1];
        double C = g_acc[2];
        out[0] = (float)(WEIGHT_D * (A - 2.0 * C) / W);
        g_acc[0] = 0.0; g_acc[1] = 0.0; g_acc[2] = 0.0;
        g_done = 0u;
    }
}

// ---------------------------------------------------------------------------
extern "C" void kernel_launch(void* const* d_in, const int* in_sizes, int n_in,
                              void* d_out, int out_size) {
    const float* mu0 = (const float*)d_in[0];
    const float* mu  = (const float*)d_in[1];
    const int* eidx  = (const int*)d_in[2];
    int n = in_sizes[0] / 3;
    int e = in_sizes[2] / 2;

    int bpack = (n + 255) / 256;
    int bfill = ((e + 3) / 4 + 255) / 256;
    fused_fill_kernel<<<bpack + bfill, 256>>>(mu0, mu, eidx, n, e, bpack);

    int nthreads = n * 4;
    node_kernel<<<(nthreads + 255) / 256, 256>>>(n, (float*)d_out);
}